// round 4
// baseline (speedup 1.0000x reference)
#include <cuda_runtime.h>
#include <cuda_bf16.h>
#include <math.h>

#define M_BATCH   32
#define D_FEAT    256
#define HW        3136
#define HW2       1568            // float2 units per channel-image
#define NGRP      16
#define GS        16
#define NPOS      100352
#define NPOS2     50176           // float2 positions per channel
#define PAIRS     136
#define EPS_W     1e-6f

#define STATS_BY  18              // grid.y for stats  (16*18 = 288 blocks)
#define APPLY_BY  37              // grid.y for apply  (16*37 = 592 blocks = 4/SM)

// Scratch (per-block partials, fully overwritten every launch)
__device__ float g_psum [NGRP][STATS_BY][GS];
__device__ float g_pprod[NGRP][STATS_BY][PAIRS];
__device__ float g_W[NGRP][GS * GS];
__device__ float g_b[NGRP][GS];          // W * mu

__device__ __forceinline__ float warp_sum(float v) {
    v += __shfl_down_sync(0xffffffffu, v, 16);
    v += __shfl_down_sync(0xffffffffu, v, 8);
    v += __shfl_down_sync(0xffffffffu, v, 4);
    v += __shfl_down_sync(0xffffffffu, v, 2);
    v += __shfl_down_sync(0xffffffffu, v, 1);
    return v;
}

// ---------------------------------------------------------------------------
// stats: warp-paired register accumulation, no smem staging, no loop barriers.
// Warps 2w and 2w+1 sweep identical positions (addresses coincide -> DRAM
// traffic stays 1x; the twin warp is served by L1/MSHR merge).
//   even warp (half 0): lower-tri ch0-7 (36) + rows 8-15 x cols 0-3 (32) + sums 0-7
//   odd  warp (half 1): lower-tri ch8-15 (36) + rows 8-15 x cols 4-7 (32) + sums 8-15
// ---------------------------------------------------------------------------
__global__ void __launch_bounds__(256, 2) stats_kernel(const float2* __restrict__ x2) {
    const int g    = blockIdx.x;
    const int tid  = threadIdx.x;
    const int wid  = tid >> 5;
    const int lane = tid & 31;
    const int wp   = wid >> 1;           // warp-pair 0..3
    const int half = wid & 1;            // warp-uniform

    const int start  = (blockIdx.y * 4 + wp) * 32 + lane;
    const int stride = STATS_BY * 4 * 32;          // 2304

    float acc[68], s[8];
#pragma unroll
    for (int i = 0; i < 68; i++) acc[i] = 0.0f;
#pragma unroll
    for (int i = 0; i < 8; i++) s[i] = 0.0f;

    const int gch = g * GS;

    for (int p = start; p < NPOS2; p += stride) {
        const int m = p / HW2;
        const int q = p - m * HW2;
        const float2* b = x2 + (size_t)(m * D_FEAT + gch) * HW2 + q;

        float2 v[16];
#pragma unroll
        for (int c = 0; c < 16; c++) v[c] = b[(size_t)c * HW2];

        if (half == 0) {
            int k = 0;
#pragma unroll
            for (int i = 0; i < 8; i++)
#pragma unroll
                for (int j = 0; j <= i; j++) {
                    acc[k] += v[i].x * v[j].x;
                    acc[k] += v[i].y * v[j].y;
                    k++;
                }
#pragma unroll
            for (int i = 0; i < 8; i++)
#pragma unroll
                for (int j = 0; j < 4; j++) {
                    acc[36 + i * 4 + j] += v[8 + i].x * v[j].x;
                    acc[36 + i * 4 + j] += v[8 + i].y * v[j].y;
                }
#pragma unroll
            for (int c = 0; c < 8; c++) s[c] += v[c].x + v[c].y;
        } else {
            int k = 0;
#pragma unroll
            for (int i = 0; i < 8; i++)
#pragma unroll
                for (int j = 0; j <= i; j++) {
                    acc[k] += v[8 + i].x * v[8 + j].x;
                    acc[k] += v[8 + i].y * v[8 + j].y;
                    k++;
                }
#pragma unroll
            for (int i = 0; i < 8; i++)
#pragma unroll
                for (int j = 0; j < 4; j++) {
                    acc[36 + i * 4 + j] += v[8 + i].x * v[4 + j].x;
                    acc[36 + i * 4 + j] += v[8 + i].y * v[4 + j].y;
                }
#pragma unroll
            for (int c = 0; c < 8; c++) s[c] += v[8 + c].x + v[8 + c].y;
        }
    }

    // ---- block reduction
    __shared__ float rsum[GS];
    __shared__ float rpair[PAIRS];
    for (int i = tid; i < GS; i += 256) rsum[i] = 0.0f;
    for (int i = tid; i < PAIRS; i += 256) rpair[i] = 0.0f;
    __syncthreads();

    if (half == 0) {
        int k = 0;
#pragma unroll
        for (int i = 0; i < 8; i++)
#pragma unroll
            for (int j = 0; j <= i; j++) {
                float v = warp_sum(acc[k]);
                if (lane == 0) atomicAdd(&rpair[i * (i + 1) / 2 + j], v);
                k++;
            }
#pragma unroll
        for (int i = 0; i < 8; i++)
#pragma unroll
            for (int j = 0; j < 4; j++) {
                float v = warp_sum(acc[36 + i * 4 + j]);
                const int r = i + 8;
                if (lane == 0) atomicAdd(&rpair[r * (r + 1) / 2 + j], v);
            }
#pragma unroll
        for (int c = 0; c < 8; c++) {
            float v = warp_sum(s[c]);
            if (lane == 0) atomicAdd(&rsum[c], v);
        }
    } else {
        int k = 0;
#pragma unroll
        for (int i = 0; i < 8; i++)
#pragma unroll
            for (int j = 0; j <= i; j++) {
                const int gi = i + 8, gj = j + 8;
                float v = warp_sum(acc[k]);
                if (lane == 0) atomicAdd(&rpair[gi * (gi + 1) / 2 + gj], v);
                k++;
            }
#pragma unroll
        for (int i = 0; i < 8; i++)
#pragma unroll
            for (int j = 0; j < 4; j++) {
                float v = warp_sum(acc[36 + i * 4 + j]);
                const int r = i + 8;
                if (lane == 0) atomicAdd(&rpair[r * (r + 1) / 2 + 4 + j], v);
            }
#pragma unroll
        for (int c = 0; c < 8; c++) {
            float v = warp_sum(s[c]);
            if (lane == 0) atomicAdd(&rsum[8 + c], v);
        }
    }
    __syncthreads();

    const int by = blockIdx.y;
    for (int i = tid; i < PAIRS; i += 256) g_pprod[g][by][i] = rpair[i];
    if (tid < GS) g_psum[g][by][tid] = rsum[tid];
}

// ---------------------------------------------------------------------------
// solve: phase 1 = cooperative 512-thread reduction of all partials into smem;
// phase 2 = one warp per group: sigma -> Cholesky -> inv(T) -> W, b.
// ---------------------------------------------------------------------------
__global__ void solve_kernel() {
    const int tid  = threadIdx.x;     // 512
    const int g    = tid >> 5;
    const int lane = tid & 31;

    __shared__ float SP[NGRP][PAIRS];
    __shared__ float MU[NGRP][GS];
    __shared__ float A [NGRP][GS][GS + 1];
    __shared__ float Wm[NGRP][GS][GS + 1];

    const float n   = (float)NPOS;
    const float nm1 = (float)(NPOS - 1);

    // phase 1: parallel partial reduction (2432 items, 18-way each)
    for (int item = tid; item < NGRP * (PAIRS + GS); item += 512) {
        const int gg = item / (PAIRS + GS);
        const int r  = item - gg * (PAIRS + GS);
        float sum = 0.0f;
        if (r < PAIRS) {
#pragma unroll
            for (int by = 0; by < STATS_BY; by++) sum += g_pprod[gg][by][r];
            SP[gg][r] = sum;
        } else {
#pragma unroll
            for (int by = 0; by < STATS_BY; by++) sum += g_psum[gg][by][r - PAIRS];
            MU[gg][r - PAIRS] = sum / n;
        }
    }
    __syncthreads();

    // phase 2: per-warp solve
    for (int k = lane; k < PAIRS; k += 32) {
        int i = (int)((sqrtf(8.0f * k + 1.0f) - 1.0f) * 0.5f);
        while ((i + 1) * (i + 2) / 2 <= k) i++;
        while (i * (i + 1) / 2 > k) i--;
        const int j = k - i * (i + 1) / 2;
        float cv = (SP[g][k] - n * MU[g][i] * MU[g][j]) / nm1;
        cv *= (1.0f - EPS_W);
        if (i == j) cv += EPS_W;
        A[g][i][j] = cv;
    }
    __syncwarp();

    // right-looking Cholesky, lanes 0-15 hold rows
    for (int j = 0; j < GS; j++) {
        if (lane == j) A[g][j][j] = sqrtf(A[g][j][j]);
        __syncwarp();
        const float dinv = 1.0f / A[g][j][j];
        if (lane > j && lane < GS) A[g][lane][j] *= dinv;
        __syncwarp();
        if (lane > j && lane < GS) {
            const float lij = A[g][lane][j];
            for (int k2 = j + 1; k2 <= lane; k2++)
                A[g][lane][k2] -= lij * A[g][k2][j];
        }
        __syncwarp();
    }

    // triangular inverse: lane j computes column j
    if (lane < GS) {
        const int j = lane;
        Wm[g][j][j] = 1.0f / A[g][j][j];
        for (int i = j + 1; i < GS; i++) {
            float s2 = 0.0f;
            for (int k2 = j; k2 < i; k2++) s2 += A[g][i][k2] * Wm[g][k2][j];
            Wm[g][i][j] = -s2 / A[g][i][i];
        }
    }
    __syncwarp();

    if (lane < GS) {
        float bb = 0.0f;
        for (int j = 0; j <= lane; j++) bb += Wm[g][lane][j] * MU[g][j];
        g_b[g][lane] = bb;
    }
    for (int e = lane; e < GS * GS; e += 32) {
        const int i = e >> 4, j = e & 15;
        g_W[g][e] = (j <= i) ? Wm[g][i][j] : 0.0f;
    }
}

// ---------------------------------------------------------------------------
// apply: float2 per iteration, streamed row accumulator -> ~50 regs,
// 4 blocks/SM (32 warps). out[i] = sum_j W[i][j]*x[j] - b[i].
// ---------------------------------------------------------------------------
__global__ void __launch_bounds__(256, 4) apply_kernel(const float2* __restrict__ x2,
                                                       float2* __restrict__ o2) {
    const int g   = blockIdx.x;
    const int tid = threadIdx.x;

    __shared__ float Ws[GS * GS];
    __shared__ float bs[GS];
    Ws[tid] = g_W[g][tid];
    if (tid < GS) bs[tid] = g_b[g][tid];
    __syncthreads();

    const int step = APPLY_BY * 256;
    for (int pos = blockIdx.y * 256 + tid; pos < NPOS2; pos += step) {
        const int m = pos / HW2;
        const int q = pos - m * HW2;
        const size_t base = (size_t)(m * D_FEAT + g * GS) * HW2 + q;

        float2 v[GS];
#pragma unroll
        for (int c = 0; c < GS; c++) v[c] = x2[base + (size_t)c * HW2];

#pragma unroll
        for (int i = 0; i < GS; i++) {
            const float bi = bs[i];
            float2 a = make_float2(-bi, -bi);
#pragma unroll
            for (int j = 0; j <= i; j++) {
                const float w = Ws[i * GS + j];
                a.x += w * v[j].x;
                a.y += w * v[j].y;
            }
            o2[base + (size_t)i * HW2] = a;
        }
    }
}

// ---------------------------------------------------------------------------
extern "C" void kernel_launch(void* const* d_in, const int* in_sizes, int n_in,
                              void* d_out, int out_size) {
    const float2* x = (const float2*)d_in[0];
    float2* out = (float2*)d_out;

    stats_kernel<<<dim3(NGRP, STATS_BY), 256>>>(x);
    solve_kernel<<<1, 512>>>();
    apply_kernel<<<dim3(NGRP, APPLY_BY), 256>>>(x, out);
}

// round 5
// speedup vs baseline: 1.0667x; 1.0667x over previous
#include <cuda_runtime.h>
#include <cuda_bf16.h>
#include <math.h>

#define D_FEAT    256
#define HW4       784             // float4 units per channel-image
#define NGRP      16
#define GS        16
#define NPOS      100352
#define NPOS4     25088
#define PAIRS     136
#define EPS_W     1e-6f

#define STATS_BY  27              // 16*27 = 432 blocks = 1 wave @ 3/SM
#define TILE      64              // float4 positions per smem tile
#define CHUNK     930             // ceil(NPOS4/27)
#define NTILES    15              // ceil(CHUNK/TILE)
#define APPLY_BY  27

// Scratch (per-block partials, fully overwritten every launch)
__device__ float g_psum [NGRP][STATS_BY][GS];
__device__ float g_pprod[NGRP][STATS_BY][PAIRS];
__device__ float g_W[NGRP][GS * GS];
__device__ float g_b[NGRP][GS];

__device__ __forceinline__ float warp_sum(float v) {
    v += __shfl_down_sync(0xffffffffu, v, 16);
    v += __shfl_down_sync(0xffffffffu, v, 8);
    v += __shfl_down_sync(0xffffffffu, v, 4);
    v += __shfl_down_sync(0xffffffffu, v, 2);
    v += __shfl_down_sync(0xffffffffu, v, 1);
    return v;
}

// ---------------------------------------------------------------------------
// stats: cp.async-staged smem tiles, double buffered, 3 blocks/SM.
// Roles (64 threads each), every role sweeps all 64 tile positions:
//   role 0: lower-tri ch0-7           (36 acc)
//   role 1: rows8-15 x cols0-3 (32) + sums ch0-3, ch8-11   (40 acc)
//   role 2: rows8-15 x cols4-7 (32) + sums ch4-7, ch12-15  (40 acc)
//   role 3: lower-tri ch8-15          (36 acc)
// ---------------------------------------------------------------------------
__global__ void __launch_bounds__(256, 3) stats_kernel(const float4* __restrict__ x4) {
    const int g   = blockIdx.x;
    const int by  = blockIdx.y;
    const int tid = threadIdx.x;

    const int P0 = by * CHUNK;
    const int P1 = (P0 + CHUNK < NPOS4) ? (P0 + CHUNK) : NPOS4;

    __shared__ float4 sbuf[2][GS * TILE];          // 2 x 16 KB
    __shared__ float rsum[GS];
    __shared__ float rpair[PAIRS];
    for (int i = tid; i < GS; i += 256) rsum[i] = 0.0f;
    for (int i = tid; i < PAIRS; i += 256) rpair[i] = 0.0f;

    const int li  = tid & 63;          // tile position this thread loads
    const int c0  = (tid >> 6) * 4;    // 4 channels per loader thread
    const int gch = g * GS;
    const unsigned sb = (unsigned)__cvta_generic_to_shared(&sbuf[0][0]);

    // ---- prologue: async-load tile 0 into slot 0
    {
        const int pos = P0 + li;
        const unsigned sz = (pos < P1) ? 16u : 0u;   // 0 => zero-fill 16B
        const int pc = (pos < P1) ? pos : P0;
        const int m = pc / HW4;
        const int q = pc - m * HW4;
        const float4* src = x4 + (size_t)(m * D_FEAT + gch + c0) * HW4 + q;
        const unsigned dst = sb + (unsigned)((c0 * TILE + li) * 16);
#pragma unroll
        for (int j = 0; j < 4; j++)
            asm volatile("cp.async.cg.shared.global [%0], [%1], 16, %2;"
                         :: "r"(dst + j * TILE * 16), "l"(src + j * HW4), "r"(sz));
        asm volatile("cp.async.commit_group;" ::: "memory");
    }

    const int role = tid >> 6;
    const int ri   = tid & 63;
    const int lane = tid & 31;

    float acc[40];
#pragma unroll
    for (int i = 0; i < 40; i++) acc[i] = 0.0f;

    for (int t = 0; t < NTILES; t++) {
        asm volatile("cp.async.wait_group 0;" ::: "memory");
        __syncthreads();

        // issue tile t+1 into the other slot (its old readers finished
        // before the sync above)
        if (t + 1 < NTILES) {
            const int pos = P0 + (t + 1) * TILE + li;
            const unsigned sz = (pos < P1) ? 16u : 0u;
            const int pc = (pos < P1) ? pos : P0;
            const int m = pc / HW4;
            const int q = pc - m * HW4;
            const float4* src = x4 + (size_t)(m * D_FEAT + gch + c0) * HW4 + q;
            const unsigned dst = sb +
                (unsigned)((((t + 1) & 1) * GS * TILE + c0 * TILE + li) * 16);
#pragma unroll
            for (int j = 0; j < 4; j++)
                asm volatile("cp.async.cg.shared.global [%0], [%1], 16, %2;"
                             :: "r"(dst + j * TILE * 16), "l"(src + j * HW4), "r"(sz));
            asm volatile("cp.async.commit_group;" ::: "memory");
        }

        const float4* Bf = sbuf[t & 1];

        if (role == 0) {
            float4 v[8];
#pragma unroll
            for (int c = 0; c < 8; c++) v[c] = Bf[c * TILE + ri];
            int k = 0;
#pragma unroll
            for (int i = 0; i < 8; i++)
#pragma unroll
                for (int j = 0; j <= i; j++) {
                    acc[k] += v[i].x * v[j].x; acc[k] += v[i].y * v[j].y;
                    acc[k] += v[i].z * v[j].z; acc[k] += v[i].w * v[j].w;
                    k++;
                }
        } else if (role == 3) {
            float4 v[8];
#pragma unroll
            for (int c = 0; c < 8; c++) v[c] = Bf[(c + 8) * TILE + ri];
            int k = 0;
#pragma unroll
            for (int i = 0; i < 8; i++)
#pragma unroll
                for (int j = 0; j <= i; j++) {
                    acc[k] += v[i].x * v[j].x; acc[k] += v[i].y * v[j].y;
                    acc[k] += v[i].z * v[j].z; acc[k] += v[i].w * v[j].w;
                    k++;
                }
        } else {
            const int cb = (role == 1) ? 0 : 4;
            float4 vc[4];
#pragma unroll
            for (int c = 0; c < 4; c++) vc[c] = Bf[(cb + c) * TILE + ri];
#pragma unroll
            for (int c = 0; c < 4; c++)
                acc[32 + c] += (vc[c].x + vc[c].y) + (vc[c].z + vc[c].w);
#pragma unroll
            for (int i = 0; i < 8; i++) {
                float4 h = Bf[(8 + i) * TILE + ri];
                // sums of hi channels: role1 -> ch8-11 (i<4), role2 -> ch12-15 (i>=4)
                if (role == 1) { if (i < 4) acc[36 + i] += (h.x + h.y) + (h.z + h.w); }
                else           { if (i >= 4) acc[36 + i - 4] += (h.x + h.y) + (h.z + h.w); }
#pragma unroll
                for (int j = 0; j < 4; j++) {
                    acc[i * 4 + j] += h.x * vc[j].x; acc[i * 4 + j] += h.y * vc[j].y;
                    acc[i * 4 + j] += h.z * vc[j].z; acc[i * 4 + j] += h.w * vc[j].w;
                }
            }
        }
    }

    // ---- reduction: warp shuffle -> shared atomics -> per-block partials
    if (role == 0) {
        int k = 0;
#pragma unroll
        for (int i = 0; i < 8; i++)
#pragma unroll
            for (int j = 0; j <= i; j++) {
                float v = warp_sum(acc[k]);
                if (lane == 0) atomicAdd(&rpair[i * (i + 1) / 2 + j], v);
                k++;
            }
    } else if (role == 3) {
        int k = 0;
#pragma unroll
        for (int i = 0; i < 8; i++)
#pragma unroll
            for (int j = 0; j <= i; j++) {
                const int gi = i + 8, gj = j + 8;
                float v = warp_sum(acc[k]);
                if (lane == 0) atomicAdd(&rpair[gi * (gi + 1) / 2 + gj], v);
                k++;
            }
    } else {
        const int cb = (role == 1) ? 0 : 4;
#pragma unroll
        for (int i = 0; i < 8; i++)
#pragma unroll
            for (int j = 0; j < 4; j++) {
                float v = warp_sum(acc[i * 4 + j]);
                const int r = i + 8;
                if (lane == 0) atomicAdd(&rpair[r * (r + 1) / 2 + cb + j], v);
            }
        // sums: lo channels cb..cb+3, hi channels (role1: 8-11, role2: 12-15)
#pragma unroll
        for (int c = 0; c < 4; c++) {
            float v = warp_sum(acc[32 + c]);
            if (lane == 0) atomicAdd(&rsum[cb + c], v);
        }
        const int hb = (role == 1) ? 8 : 12;
#pragma unroll
        for (int c = 0; c < 4; c++) {
            float v = warp_sum(acc[36 + c]);
            if (lane == 0) atomicAdd(&rsum[hb + c], v);
        }
    }
    __syncthreads();

    for (int i = tid; i < PAIRS; i += 256) g_pprod[g][by][i] = rpair[i];
    if (tid < GS) g_psum[g][by][tid] = rsum[tid];
}

// ---------------------------------------------------------------------------
// solve: phase 1 parallel partial reduction; phase 2 per-warp Cholesky + inv.
// ---------------------------------------------------------------------------
__global__ void solve_kernel() {
    const int tid  = threadIdx.x;     // 512
    const int g    = tid >> 5;
    const int lane = tid & 31;

    __shared__ float SP[NGRP][PAIRS];
    __shared__ float MU[NGRP][GS];
    __shared__ float A [NGRP][GS][GS + 1];
    __shared__ float Wm[NGRP][GS][GS + 1];

    const float n   = (float)NPOS;
    const float nm1 = (float)(NPOS - 1);

    for (int item = tid; item < NGRP * (PAIRS + GS); item += 512) {
        const int gg = item / (PAIRS + GS);
        const int r  = item - gg * (PAIRS + GS);
        float sum = 0.0f;
        if (r < PAIRS) {
#pragma unroll
            for (int by = 0; by < STATS_BY; by++) sum += g_pprod[gg][by][r];
            SP[gg][r] = sum;
        } else {
#pragma unroll
            for (int by = 0; by < STATS_BY; by++) sum += g_psum[gg][by][r - PAIRS];
            MU[gg][r - PAIRS] = sum / n;
        }
    }
    __syncthreads();

    for (int k = lane; k < PAIRS; k += 32) {
        int i = (int)((sqrtf(8.0f * k + 1.0f) - 1.0f) * 0.5f);
        while ((i + 1) * (i + 2) / 2 <= k) i++;
        while (i * (i + 1) / 2 > k) i--;
        const int j = k - i * (i + 1) / 2;
        float cv = (SP[g][k] - n * MU[g][i] * MU[g][j]) / nm1;
        cv *= (1.0f - EPS_W);
        if (i == j) cv += EPS_W;
        A[g][i][j] = cv;
    }
    __syncwarp();

    for (int j = 0; j < GS; j++) {
        if (lane == j) A[g][j][j] = sqrtf(A[g][j][j]);
        __syncwarp();
        const float dinv = 1.0f / A[g][j][j];
        if (lane > j && lane < GS) A[g][lane][j] *= dinv;
        __syncwarp();
        if (lane > j && lane < GS) {
            const float lij = A[g][lane][j];
            for (int k2 = j + 1; k2 <= lane; k2++)
                A[g][lane][k2] -= lij * A[g][k2][j];
        }
        __syncwarp();
    }

    if (lane < GS) {
        const int j = lane;
        Wm[g][j][j] = 1.0f / A[g][j][j];
        for (int i = j + 1; i < GS; i++) {
            float s2 = 0.0f;
            for (int k2 = j; k2 < i; k2++) s2 += A[g][i][k2] * Wm[g][k2][j];
            Wm[g][i][j] = -s2 / A[g][i][i];
        }
    }
    __syncwarp();

    if (lane < GS) {
        float bb = 0.0f;
        for (int j = 0; j <= lane; j++) bb += Wm[g][lane][j] * MU[g][j];
        g_b[g][lane] = bb;
    }
    for (int e = lane; e < GS * GS; e += 32) {
        const int i = e >> 4, j = e & 15;
        g_W[g][e] = (j <= i) ? Wm[g][i][j] : 0.0f;
    }
}

// ---------------------------------------------------------------------------
// apply: batched 16x float4 loads (MLP 16), streamed row acc, bias fold.
// 3 blocks/SM, one wave (432 blocks).
// ---------------------------------------------------------------------------
__global__ void __launch_bounds__(256, 3) apply_kernel(const float4* __restrict__ x4,
                                                       float4* __restrict__ o4) {
    const int g   = blockIdx.x;
    const int tid = threadIdx.x;

    __shared__ float Ws[GS * GS];
    __shared__ float bs[GS];
    Ws[tid] = g_W[g][tid];
    if (tid < GS) bs[tid] = g_b[g][tid];
    __syncthreads();

    const int step = APPLY_BY * 256;
    for (int pos = blockIdx.y * 256 + tid; pos < NPOS4; pos += step) {
        const int m = pos / HW4;
        const int q = pos - m * HW4;
        const int base = (m * D_FEAT + g * GS) * HW4 + q;

        float4 v[GS];
#pragma unroll
        for (int c = 0; c < GS; c++) v[c] = x4[base + c * HW4];

#pragma unroll
        for (int i = 0; i < GS; i++) {
            const float bi = bs[i];
            float4 a = make_float4(-bi, -bi, -bi, -bi);
#pragma unroll
            for (int j = 0; j <= i; j++) {
                const float w = Ws[i * GS + j];
                a.x += w * v[j].x; a.y += w * v[j].y;
                a.z += w * v[j].z; a.w += w * v[j].w;
            }
            o4[base + i * HW4] = a;
        }
    }
}

// ---------------------------------------------------------------------------
extern "C" void kernel_launch(void* const* d_in, const int* in_sizes, int n_in,
                              void* d_out, int out_size) {
    const float4* x = (const float4*)d_in[0];
    float4* out = (float4*)d_out;

    stats_kernel<<<dim3(NGRP, STATS_BY), 256>>>(x);
    solve_kernel<<<1, 512>>>();
    apply_kernel<<<dim3(NGRP, APPLY_BY), 256>>>(x, out);
}